// round 4
// baseline (speedup 1.0000x reference)
#include <cuda_runtime.h>
#include <math.h>

#define N_CODES 16384
#define DDIM 32
#define T_TOK 8192
#define NSTRIP 128   // N_CODES / 128 code-strips per token

// ---------------- scratch (static __device__, allowed) ----------------
__device__ float  g_zf[T_TOK * DDIM];              // normalized z, token-major
__device__ float  g_zn2[T_TOK];                    // sum zf^2 per token
__device__ float  g_en[N_CODES * DDIM];            // normalized embedding
__device__ float  g_en2[N_CODES];                  // sum en^2 per code
__device__ float  g_fa[(size_t)T_TOK * N_CODES];   // 512MB: fa = -100*d, full matrix
__device__ float4 g_pm[T_TOK * NSTRIP];            // per (token,strip): m, S, W', idx(bits)
__device__ float  g_lse[T_TOK];
__device__ float  g_sent[T_TOK];                   // per-token sample entropy
__device__ int    g_idx[T_TOK];
__device__ float  g_avgpart[16 * N_CODES];         // avg_probs partials (16 token slabs)
__device__ float  g_vqtok[T_TOK];                  // per-token sum (zq-zb)^2
__device__ float  g_red[16];                       // final partials

// ---------------- f32x2 packed math (sm_100+) ----------------
#define PACK2(d, lo, hi)   asm("mov.b64 %0, {%1, %2};" : "=l"(d) : "f"(lo), "f"(hi))
#define UNPACK2(lo, hi, s) asm("mov.b64 {%0, %1}, %2;" : "=f"(lo), "=f"(hi) : "l"(s))
#define FMA2(d, a, b, c)   asm("fma.rn.f32x2 %0, %1, %2, %3;" : "=l"(d) : "l"(a), "l"(b), "l"(c))

// ---------------- K0: normalize z (gather from (b,c,h,w)) ----------------
__global__ void znorm_kernel(const float* __restrict__ z) {
    int t = blockIdx.x * 8 + (threadIdx.x >> 5);
    int c = threadIdx.x & 31;
    int b = t >> 8, hw = t & 255;
    float x = z[b * 8192 + c * 256 + hw];
    float s = x * x;
#pragma unroll
    for (int m = 16; m; m >>= 1) s += __shfl_xor_sync(0xffffffffu, s, m);
    float n = sqrtf(s);
    float v = x / fmaxf(n, 1e-12f);
    g_zf[t * DDIM + c] = v;
    float s2 = v * v;
#pragma unroll
    for (int m = 16; m; m >>= 1) s2 += __shfl_xor_sync(0xffffffffu, s2, m);
    if (c == 0) g_zn2[t] = s2;
}

__global__ void enorm_kernel(const float* __restrict__ e) {
    int nrow = blockIdx.x * 8 + (threadIdx.x >> 5);
    int c = threadIdx.x & 31;
    float x = e[nrow * DDIM + c];
    float s = x * x;
#pragma unroll
    for (int m = 16; m; m >>= 1) s += __shfl_xor_sync(0xffffffffu, s, m);
    float n = sqrtf(s);
    float v = x / fmaxf(n, 1e-12f);
    g_en[nrow * DDIM + c] = v;
    float s2 = v * v;
#pragma unroll
    for (int m = 16; m; m >>= 1) s2 += __shfl_xor_sync(0xffffffffu, s2, m);
    if (c == 0) g_en2[nrow] = s2;
}

// ---------------- init (positional filler so p1 is the profiled 4th launch) ----------------
__global__ void init_kernel() {
    int i = blockIdx.x * 256 + threadIdx.x;
    if (i < 16 * N_CODES) g_avgpart[i] = 0.f;
}

// ---------------- P1: 128x128 fp32 GEMM tile + fa store + strip stats ----------------
__global__ void __launch_bounds__(256) p1_kernel() {
    __shared__ float zs[DDIM][128];   // k-major
    __shared__ float es[DDIM][128];   // k-major
    const int tid = threadIdx.x;
    const int c0 = blockIdx.x * 128;
    const int t0 = blockIdx.y * 128;

    const float4* zsrc = (const float4*)(g_zf + (size_t)t0 * DDIM);
    const float4* esrc = (const float4*)(g_en + (size_t)c0 * DDIM);
#pragma unroll
    for (int q = 0; q < 4; q++) {
        int fi = tid + q * 256;
        int row = fi >> 3;
        int col = (fi & 7) << 2;
        float4 v = zsrc[fi];
        zs[col][row] = v.x; zs[col + 1][row] = v.y; zs[col + 2][row] = v.z; zs[col + 3][row] = v.w;
        float4 w = esrc[fi];
        es[col][row] = w.x; es[col + 1][row] = w.y; es[col + 2][row] = w.z; es[col + 3][row] = w.w;
    }
    __syncthreads();

    const int tx = tid & 15, ty = tid >> 4;
    unsigned long long acc[8][4];
#pragma unroll
    for (int i = 0; i < 8; i++)
#pragma unroll
        for (int j = 0; j < 4; j++) acc[i][j] = 0ull;  // (0.f, 0.f)

#pragma unroll 8
    for (int k = 0; k < DDIM; k++) {
        // e operands: float4 == two f32x2 pairs, zero-MOV reinterpret
        ulonglong2 e01 = *(const ulonglong2*)&es[k][tx * 8];
        ulonglong2 e23 = *(const ulonglong2*)&es[k][tx * 8 + 4];
        float4 za  = *(const float4*)&zs[k][ty * 8];
        float4 zb4 = *(const float4*)&zs[k][ty * 8 + 4];
        float zv[8] = {za.x, za.y, za.z, za.w, zb4.x, zb4.y, zb4.z, zb4.w};
#pragma unroll
        for (int i = 0; i < 8; i++) {
            unsigned long long zz;
            PACK2(zz, zv[i], zv[i]);
            FMA2(acc[i][0], e01.x, zz, acc[i][0]);
            FMA2(acc[i][1], e01.y, zz, acc[i][1]);
            FMA2(acc[i][2], e23.x, zz, acc[i][2]);
            FMA2(acc[i][3], e23.y, zz, acc[i][3]);
        }
    }

    // epilogue: fa store (streaming) + per-strip (max fa == min d, S, W', idx)
    float e2v[8];
#pragma unroll
    for (int j = 0; j < 8; j++) e2v[j] = g_en2[c0 + tx * 8 + j];

#pragma unroll
    for (int i = 0; i < 8; i++) {
        int t = t0 + ty * 8 + i;
        float zi2 = g_zn2[t];
        float fav[8];
        float m = -3.4e38f;
        int midx = 0;
#pragma unroll
        for (int jp = 0; jp < 4; jp++) {
            float lo, hi;
            UNPACK2(lo, hi, acc[i][jp]);
            float f0 = -100.0f * (zi2 + e2v[2 * jp]     - 2.0f * lo);
            float f1 = -100.0f * (zi2 + e2v[2 * jp + 1] - 2.0f * hi);
            fav[2 * jp]     = f0;
            fav[2 * jp + 1] = f1;
            if (f0 > m) { m = f0; midx = c0 + tx * 8 + 2 * jp; }
            if (f1 > m) { m = f1; midx = c0 + tx * 8 + 2 * jp + 1; }
        }
        float* fr = g_fa + (size_t)t * N_CODES + c0 + tx * 8;
        __stcs((float4*)fr,       make_float4(fav[0], fav[1], fav[2], fav[3]));
        __stcs((float4*)(fr + 4), make_float4(fav[4], fav[5], fav[6], fav[7]));

        // single combined (max, idx) shuffle chain across 16 lanes
#pragma unroll
        for (int s = 1; s < 16; s <<= 1) {
            float om = __shfl_xor_sync(0xffffffffu, m, s);
            int   oi = __shfl_xor_sync(0xffffffffu, midx, s);
            if (om > m || (om == m && oi < midx)) { m = om; midx = oi; }
        }
        float S = 0.f, W = 0.f;   // W' = sum (fa-m) e^(fa-m)
#pragma unroll
        for (int j = 0; j < 8; j++) {
            float x = fav[j] - m;
            float e = __expf(x);
            S += e;
            W = fmaf(x, e, W);
        }
#pragma unroll
        for (int s = 1; s < 16; s <<= 1) {
            S += __shfl_xor_sync(0xffffffffu, S, s);
            W += __shfl_xor_sync(0xffffffffu, W, s);
        }
        if (tx == 0)
            g_pm[(size_t)t * NSTRIP + blockIdx.x] =
                make_float4(m, S, W, __int_as_float(midx));
    }
}

// ---------------- merge strips per token -> LSE, sample entropy, argmin ----------------
__global__ void merge_kernel() {
    int t = blockIdx.x * 8 + (threadIdx.x >> 5);
    int lane = threadIdx.x & 31;
    float4 v[4];
#pragma unroll
    for (int q = 0; q < 4; q++)
        v[q] = g_pm[(size_t)t * NSTRIP + lane + q * 32];

    // global max fa (== min distance) + index
    float m = v[0].x; int midx = __float_as_int(v[0].w);
#pragma unroll
    for (int q = 1; q < 4; q++) {
        int oi = __float_as_int(v[q].w);
        if (v[q].x > m || (v[q].x == m && oi < midx)) { m = v[q].x; midx = oi; }
    }
#pragma unroll
    for (int s = 1; s < 32; s <<= 1) {
        float om = __shfl_xor_sync(0xffffffffu, m, s);
        int   oi = __shfl_xor_sync(0xffffffffu, midx, s);
        if (om > m || (om == m && oi < midx)) { m = om; midx = oi; }
    }
    float S = 0.f, W = 0.f;
#pragma unroll
    for (int q = 0; q < 4; q++) {
        float dm = v[q].x - m;
        float sc = __expf(dm);
        S += v[q].y * sc;
        W += (v[q].z + dm * v[q].y) * sc;
    }
#pragma unroll
    for (int s = 1; s < 32; s <<= 1) {
        S += __shfl_xor_sync(0xffffffffu, S, s);
        W += __shfl_xor_sync(0xffffffffu, W, s);
    }
    if (lane == 0) {
        float lS = logf(S);
        g_lse[t]  = m + lS;
        g_sent[t] = lS - W / S;     // = LSE - sum(p*fa), cancellation-safe
        g_idx[t]  = midx;
    }
}

// ---------------- P2: probs from stored fa -> avg_probs partials ----------------
__global__ void __launch_bounds__(256) p2_kernel() {
    __shared__ float slse[512];
    int tid = threadIdx.x;
    int c = blockIdx.x * 256 + tid;
    int t0 = blockIdx.y * 512;
    for (int i = tid; i < 512; i += 256) slse[i] = g_lse[t0 + i];
    __syncthreads();
    float a0 = 0.f, a1 = 0.f, a2 = 0.f, a3 = 0.f;
    const float* p = g_fa + (size_t)t0 * N_CODES + c;
#pragma unroll 4
    for (int t = 0; t < 512; t += 4) {
        a0 += __expf(__ldcs(p + (size_t)t * N_CODES)       - slse[t]);
        a1 += __expf(__ldcs(p + (size_t)(t + 1) * N_CODES) - slse[t + 1]);
        a2 += __expf(__ldcs(p + (size_t)(t + 2) * N_CODES) - slse[t + 2]);
        a3 += __expf(__ldcs(p + (size_t)(t + 3) * N_CODES) - slse[t + 3]);
    }
    g_avgpart[(size_t)blockIdx.y * N_CODES + c] = (a0 + a1) + (a2 + a3);
}

// ---------------- quantize: z_q_st output + vq partials ----------------
__global__ void quant_kernel(float* __restrict__ out) {
    int t = blockIdx.x * 8 + (threadIdx.x >> 5);
    int c = threadIdx.x & 31;
    float zb = g_zf[t * DDIM + c];
    float e = g_en[(size_t)g_idx[t] * DDIM + c];
    float o = zb + (e - zb);                 // z_q_st forward value
    int b = t >> 8, hw = t & 255;
    out[b * 8192 + c * 256 + hw] = o;
    float df = e - zb;
    float s = df * df;
#pragma unroll
    for (int m = 16; m; m >>= 1) s += __shfl_xor_sync(0xffffffffu, s, m);
    if (c == 0) g_vqtok[t] = s;
}

// ---------------- finalA: parallel partials (10 blocks) ----------------
__global__ void finalA_kernel() {
    __shared__ float red[256];
    int tid = threadIdx.x;
    int b = blockIdx.x;
    float acc = 0.f;
    if (b < 8) {
        // entropy over 2048 codes per block
        int n0 = b * 2048;
        for (int n = n0 + tid; n < n0 + 2048; n += 256) {
            float ap = 0.f;
#pragma unroll
            for (int j = 0; j < 16; j++) ap += g_avgpart[j * N_CODES + n];
            ap *= (1.0f / 8192.0f);
            acc -= ap * logf(ap + 1e-5f);
        }
    } else if (b == 8) {
        for (int t = tid; t < T_TOK; t += 256) acc += g_vqtok[t];
    } else {
        for (int t = tid; t < T_TOK; t += 256) acc += g_sent[t];
    }
    red[tid] = acc; __syncthreads();
    for (int s = 128; s; s >>= 1) { if (tid < s) red[tid] += red[tid + s]; __syncthreads(); }
    if (tid == 0) g_red[b] = red[0];
}

// ---------------- finalB: combine -> 3 loss scalars ----------------
__global__ void finalB_kernel(float* __restrict__ out, int out_size) {
    float ent = 0.f;
#pragma unroll
    for (int j = 0; j < 8; j++) ent += g_red[j];
    float vq = g_red[8] / 262144.0f;          // mean over 32*16*16*32 elements
    float se = g_red[9] / 8192.0f;            // sample_entropy
    out[out_size - 3] = vq;                   // vq_loss
    out[out_size - 2] = 0.25f * vq;           // commit_loss
    out[out_size - 1] = 0.1f * (se - ent);    // ENT_RATIO * (sample - avg)
}

// ---------------- launcher ----------------
extern "C" void kernel_launch(void* const* d_in, const int* in_sizes, int n_in,
                              void* d_out, int out_size) {
    const float* z   = (const float*)d_in[0];   // (32,32,16,16) f32
    const float* emb = (const float*)d_in[1];   // (16384,32) f32
    float* out = (float*)d_out;                 // 262144 image + 3 losses

    znorm_kernel<<<T_TOK / 8, 256>>>(z);
    enorm_kernel<<<N_CODES / 8, 256>>>(emb);
    init_kernel<<<(16 * N_CODES) / 256, 256>>>();   // filler: p1 is 4th (profiled) launch

    p1_kernel<<<dim3(NSTRIP, T_TOK / 128), 256>>>();
    merge_kernel<<<T_TOK / 8, 256>>>();
    p2_kernel<<<dim3(N_CODES / 256, T_TOK / 512), 256>>>();

    quant_kernel<<<T_TOK / 8, 256>>>(out);
    finalA_kernel<<<10, 256>>>();
    finalB_kernel<<<1, 32>>>(out, out_size);
}

// round 5
// speedup vs baseline: 1.0807x; 1.0807x over previous
#include <cuda_runtime.h>
#include <math.h>

#define N_CODES 16384
#define DDIM 32
#define T_TOK 8192
#define NSTRIP 128   // N_CODES / 128 code-strips per token

// ---------------- scratch (static __device__, allowed) ----------------
__device__ float  g_zf[T_TOK * DDIM];              // normalized z, token-major
__device__ float  g_zn2[T_TOK];                    // sum zf^2 per token
__device__ float  g_en[N_CODES * DDIM];            // normalized embedding
__device__ float  g_en2[N_CODES];                  // sum en^2 per code
__device__ float  g_fa[(size_t)T_TOK * N_CODES];   // 512MB: fa = -100*d, full matrix
__device__ float4 g_pm[T_TOK * NSTRIP];            // per (token,strip): m, S, W', idx(bits)
__device__ float  g_lse[T_TOK];
__device__ float  g_sent[T_TOK];                   // per-token sample entropy
__device__ int    g_idx[T_TOK];
__device__ float  g_avgpart[16 * N_CODES];         // avg_probs partials (16 token slabs)
__device__ float  g_vqtok[T_TOK];                  // per-token sum (zq-zb)^2
__device__ float  g_red[16];                       // final partials

// ---------------- f32x2 packed math (sm_100+) ----------------
#define UNPACK2(lo, hi, s) asm("mov.b64 {%0, %1}, %2;" : "=f"(lo), "=f"(hi) : "l"(s))
#define FMA2(d, a, b, c)   asm("fma.rn.f32x2 %0, %1, %2, %3;" : "=l"(d) : "l"(a), "l"(b), "l"(c))

// ---------------- K0: normalize z (gather from (b,c,h,w)) ----------------
__global__ void znorm_kernel(const float* __restrict__ z) {
    int t = blockIdx.x * 8 + (threadIdx.x >> 5);
    int c = threadIdx.x & 31;
    int b = t >> 8, hw = t & 255;
    float x = z[b * 8192 + c * 256 + hw];
    float s = x * x;
#pragma unroll
    for (int m = 16; m; m >>= 1) s += __shfl_xor_sync(0xffffffffu, s, m);
    float n = sqrtf(s);
    float v = x / fmaxf(n, 1e-12f);
    g_zf[t * DDIM + c] = v;
    float s2 = v * v;
#pragma unroll
    for (int m = 16; m; m >>= 1) s2 += __shfl_xor_sync(0xffffffffu, s2, m);
    if (c == 0) g_zn2[t] = s2;
}

__global__ void enorm_kernel(const float* __restrict__ e) {
    int nrow = blockIdx.x * 8 + (threadIdx.x >> 5);
    int c = threadIdx.x & 31;
    float x = e[nrow * DDIM + c];
    float s = x * x;
#pragma unroll
    for (int m = 16; m; m >>= 1) s += __shfl_xor_sync(0xffffffffu, s, m);
    float n = sqrtf(s);
    float v = x / fmaxf(n, 1e-12f);
    g_en[nrow * DDIM + c] = v;
    float s2 = v * v;
#pragma unroll
    for (int m = 16; m; m >>= 1) s2 += __shfl_xor_sync(0xffffffffu, s2, m);
    if (c == 0) g_en2[nrow] = s2;
}

// ---------------- init (positional filler so p1 is the profiled 4th launch) ----------------
__global__ void init_kernel() {
    int i = blockIdx.x * 256 + threadIdx.x;
    if (i < 16 * N_CODES) g_avgpart[i] = 0.f;
}

// ---------------- P1: 128x128 fp32 GEMM tile + fa store + strip stats ----------------
__global__ void __launch_bounds__(256, 2) p1_kernel() {
    __shared__ float4 esA[DDIM][16];    // codes 8t..8t+3 at dim k  (conflict-free)
    __shared__ float4 esB[DDIM][16];    // codes 8t+4..8t+7 at dim k
    __shared__ float2 zdup[DDIM][128];  // z duplicated: (v,v) -> ready f32x2 operand
    const int tid = threadIdx.x;
    const int c0 = blockIdx.x * 128;
    const int t0 = blockIdx.y * 128;

    const float4* zsrc = (const float4*)(g_zf + (size_t)t0 * DDIM);
    const float4* esrc = (const float4*)(g_en + (size_t)c0 * DDIM);
#pragma unroll
    for (int q = 0; q < 4; q++) {
        int fi = tid + q * 256;
        int row = fi >> 3;          // 0..127
        int col = (fi & 7) << 2;    // k base
        float4 v = zsrc[fi];
        zdup[col + 0][row] = make_float2(v.x, v.x);
        zdup[col + 1][row] = make_float2(v.y, v.y);
        zdup[col + 2][row] = make_float2(v.z, v.z);
        zdup[col + 3][row] = make_float2(v.w, v.w);
        float4 w = esrc[fi];
        int t = row >> 3;           // chunk 0..15
        int sub = row & 7;
        float* dst = (sub < 4) ? (float*)esA : (float*)esB;
        int p = sub & 3;
        dst[((col + 0) * 16 + t) * 4 + p] = w.x;
        dst[((col + 1) * 16 + t) * 4 + p] = w.y;
        dst[((col + 2) * 16 + t) * 4 + p] = w.z;
        dst[((col + 3) * 16 + t) * 4 + p] = w.w;
    }
    __syncthreads();

    const int tx = tid & 15, ty = tid >> 4;
    unsigned long long acc[8][4];
#pragma unroll
    for (int i = 0; i < 8; i++)
#pragma unroll
        for (int j = 0; j < 4; j++) acc[i][j] = 0ull;

#pragma unroll 8
    for (int k = 0; k < DDIM; k++) {
        ulonglong2 e01 = *(const ulonglong2*)&esA[k][tx];   // pairs (8tx,8tx+1),(8tx+2,8tx+3)
        ulonglong2 e23 = *(const ulonglong2*)&esB[k][tx];   // pairs (8tx+4,5),(8tx+6,7)
        ulonglong2 zp0 = *(const ulonglong2*)&zdup[k][ty * 8];
        ulonglong2 zp1 = *(const ulonglong2*)&zdup[k][ty * 8 + 2];
        ulonglong2 zp2 = *(const ulonglong2*)&zdup[k][ty * 8 + 4];
        ulonglong2 zp3 = *(const ulonglong2*)&zdup[k][ty * 8 + 6];
        unsigned long long zz[8] = {zp0.x, zp0.y, zp1.x, zp1.y,
                                    zp2.x, zp2.y, zp3.x, zp3.y};
#pragma unroll
        for (int i = 0; i < 8; i++) {
            FMA2(acc[i][0], e01.x, zz[i], acc[i][0]);
            FMA2(acc[i][1], e01.y, zz[i], acc[i][1]);
            FMA2(acc[i][2], e23.x, zz[i], acc[i][2]);
            FMA2(acc[i][3], e23.y, zz[i], acc[i][3]);
        }
    }

    // epilogue: fa store (streaming) + per-strip (max fa == min d, S, W', idx)
    float e2v[8];
#pragma unroll
    for (int j = 0; j < 8; j++) e2v[j] = g_en2[c0 + tx * 8 + j];

    for (int i = 0; i < 8; i++) {
        int t = t0 + ty * 8 + i;
        float zi2 = g_zn2[t];
        float fav[8];
        float m = -3.4e38f;
        int midx = 0;
#pragma unroll
        for (int jp = 0; jp < 4; jp++) {
            float lo, hi;
            UNPACK2(lo, hi, acc[i][jp]);
            float f0 = -100.0f * (zi2 + e2v[2 * jp]     - 2.0f * lo);
            float f1 = -100.0f * (zi2 + e2v[2 * jp + 1] - 2.0f * hi);
            fav[2 * jp]     = f0;
            fav[2 * jp + 1] = f1;
            if (f0 > m) { m = f0; midx = c0 + tx * 8 + 2 * jp; }
            if (f1 > m) { m = f1; midx = c0 + tx * 8 + 2 * jp + 1; }
        }
        float* fr = g_fa + (size_t)t * N_CODES + c0 + tx * 8;
        __stcs((float4*)fr,       make_float4(fav[0], fav[1], fav[2], fav[3]));
        __stcs((float4*)(fr + 4), make_float4(fav[4], fav[5], fav[6], fav[7]));

        // single combined (max, idx) shuffle chain across 16 lanes
#pragma unroll
        for (int s = 1; s < 16; s <<= 1) {
            float om = __shfl_xor_sync(0xffffffffu, m, s);
            int   oi = __shfl_xor_sync(0xffffffffu, midx, s);
            if (om > m || (om == m && oi < midx)) { m = om; midx = oi; }
        }
        float S = 0.f, W = 0.f;   // W' = sum (fa-m) e^(fa-m)
#pragma unroll
        for (int j = 0; j < 8; j++) {
            float x = fav[j] - m;
            float e = __expf(x);
            S += e;
            W = fmaf(x, e, W);
        }
#pragma unroll
        for (int s = 1; s < 16; s <<= 1) {
            S += __shfl_xor_sync(0xffffffffu, S, s);
            W += __shfl_xor_sync(0xffffffffu, W, s);
        }
        if (tx == 0)
            g_pm[(size_t)t * NSTRIP + blockIdx.x] =
                make_float4(m, S, W, __int_as_float(midx));
    }
}

// ---------------- merge strips per token -> LSE, sample entropy, argmin ----------------
__global__ void merge_kernel() {
    int t = blockIdx.x * 8 + (threadIdx.x >> 5);
    int lane = threadIdx.x & 31;
    float4 v[4];
#pragma unroll
    for (int q = 0; q < 4; q++)
        v[q] = g_pm[(size_t)t * NSTRIP + lane + q * 32];

    float m = v[0].x; int midx = __float_as_int(v[0].w);
#pragma unroll
    for (int q = 1; q < 4; q++) {
        int oi = __float_as_int(v[q].w);
        if (v[q].x > m || (v[q].x == m && oi < midx)) { m = v[q].x; midx = oi; }
    }
#pragma unroll
    for (int s = 1; s < 32; s <<= 1) {
        float om = __shfl_xor_sync(0xffffffffu, m, s);
        int   oi = __shfl_xor_sync(0xffffffffu, midx, s);
        if (om > m || (om == m && oi < midx)) { m = om; midx = oi; }
    }
    float S = 0.f, W = 0.f;
#pragma unroll
    for (int q = 0; q < 4; q++) {
        float dm = v[q].x - m;
        float sc = __expf(dm);
        S += v[q].y * sc;
        W += (v[q].z + dm * v[q].y) * sc;
    }
#pragma unroll
    for (int s = 1; s < 32; s <<= 1) {
        S += __shfl_xor_sync(0xffffffffu, S, s);
        W += __shfl_xor_sync(0xffffffffu, W, s);
    }
    if (lane == 0) {
        float lS = logf(S);
        g_lse[t]  = m + lS;
        g_sent[t] = lS - W / S;
        g_idx[t]  = midx;
    }
}

// ---------------- P2: probs from stored fa -> avg_probs partials ----------------
__global__ void __launch_bounds__(256) p2_kernel() {
    __shared__ float slse[512];
    int tid = threadIdx.x;
    int c = blockIdx.x * 256 + tid;
    int t0 = blockIdx.y * 512;
    for (int i = tid; i < 512; i += 256) slse[i] = g_lse[t0 + i];
    __syncthreads();
    float a0 = 0.f, a1 = 0.f, a2 = 0.f, a3 = 0.f;
    const float* p = g_fa + (size_t)t0 * N_CODES + c;
#pragma unroll 4
    for (int t = 0; t < 512; t += 4) {
        a0 += __expf(__ldcs(p + (size_t)t * N_CODES)       - slse[t]);
        a1 += __expf(__ldcs(p + (size_t)(t + 1) * N_CODES) - slse[t + 1]);
        a2 += __expf(__ldcs(p + (size_t)(t + 2) * N_CODES) - slse[t + 2]);
        a3 += __expf(__ldcs(p + (size_t)(t + 3) * N_CODES) - slse[t + 3]);
    }
    g_avgpart[(size_t)blockIdx.y * N_CODES + c] = (a0 + a1) + (a2 + a3);
}

// ---------------- quantize: z_q_st output + vq partials ----------------
__global__ void quant_kernel(float* __restrict__ out) {
    int t = blockIdx.x * 8 + (threadIdx.x >> 5);
    int c = threadIdx.x & 31;
    float zb = g_zf[t * DDIM + c];
    float e = g_en[(size_t)g_idx[t] * DDIM + c];
    float o = zb + (e - zb);
    int b = t >> 8, hw = t & 255;
    out[b * 8192 + c * 256 + hw] = o;
    float df = e - zb;
    float s = df * df;
#pragma unroll
    for (int m = 16; m; m >>= 1) s += __shfl_xor_sync(0xffffffffu, s, m);
    if (c == 0) g_vqtok[t] = s;
}

// ---------------- finalA: parallel partials (10 blocks) ----------------
__global__ void finalA_kernel() {
    __shared__ float red[256];
    int tid = threadIdx.x;
    int b = blockIdx.x;
    float acc = 0.f;
    if (b < 8) {
        int n0 = b * 2048;
        for (int n = n0 + tid; n < n0 + 2048; n += 256) {
            float ap = 0.f;
#pragma unroll
            for (int j = 0; j < 16; j++) ap += g_avgpart[j * N_CODES + n];
            ap *= (1.0f / 8192.0f);
            acc -= ap * logf(ap + 1e-5f);
        }
    } else if (b == 8) {
        for (int t = tid; t < T_TOK; t += 256) acc += g_vqtok[t];
    } else {
        for (int t = tid; t < T_TOK; t += 256) acc += g_sent[t];
    }
    red[tid] = acc; __syncthreads();
    for (int s = 128; s; s >>= 1) { if (tid < s) red[tid] += red[tid + s]; __syncthreads(); }
    if (tid == 0) g_red[b] = red[0];
}

// ---------------- finalB: combine -> 3 loss scalars ----------------
__global__ void finalB_kernel(float* __restrict__ out, int out_size) {
    float ent = 0.f;
#pragma unroll
    for (int j = 0; j < 8; j++) ent += g_red[j];
    float vq = g_red[8] / 262144.0f;
    float se = g_red[9] / 8192.0f;
    out[out_size - 3] = vq;
    out[out_size - 2] = 0.25f * vq;
    out[out_size - 1] = 0.1f * (se - ent);
}

// ---------------- launcher ----------------
extern "C" void kernel_launch(void* const* d_in, const int* in_sizes, int n_in,
                              void* d_out, int out_size) {
    const float* z   = (const float*)d_in[0];
    const float* emb = (const float*)d_in[1];
    float* out = (float*)d_out;

    znorm_kernel<<<T_TOK / 8, 256>>>(z);
    enorm_kernel<<<N_CODES / 8, 256>>>(emb);
    init_kernel<<<(16 * N_CODES) / 256, 256>>>();   // filler: p1 is 4th (profiled) launch

    p1_kernel<<<dim3(NSTRIP, T_TOK / 128), 256>>>();
    merge_kernel<<<T_TOK / 8, 256>>>();
    p2_kernel<<<dim3(N_CODES / 256, T_TOK / 512), 256>>>();

    quant_kernel<<<T_TOK / 8, 256>>>(out);
    finalA_kernel<<<10, 256>>>();
    finalB_kernel<<<1, 32>>>(out, out_size);
}

// round 6
// speedup vs baseline: 1.8127x; 1.6773x over previous
#include <cuda_runtime.h>
#include <cuda_fp16.h>
#include <math.h>

#define N_CODES 16384
#define DDIM 32
#define T_TOK 8192
#define NSTRIP 128   // N_CODES / 128 code-strips per token

// ---------------- scratch (static __device__, allowed) ----------------
__device__ float  g_zf[T_TOK * DDIM];              // normalized z, token-major
__device__ float  g_zn2[T_TOK];                    // sum zf^2 per token
__device__ float  g_en[N_CODES * DDIM];            // normalized embedding
__device__ float  g_en2[N_CODES];                  // sum en^2 per code
__device__ __half g_eh[(size_t)T_TOK * N_CODES];   // 256MB: exp(fa - m_strip) fp16
__device__ float4 g_pm[T_TOK * NSTRIP];            // per (token,strip): m, S, W', idx(bits)
__device__ float  g_scale[T_TOK * NSTRIP];         // exp(m_strip - lse_t)
__device__ float  g_lse[T_TOK];
__device__ float  g_sent[T_TOK];                   // per-token sample entropy
__device__ int    g_idx[T_TOK];
__device__ float  g_avgpart[16 * N_CODES];         // avg_probs partials (16 token slabs)
__device__ float  g_vqtok[T_TOK];                  // per-token sum (zq-zb)^2
__device__ float  g_red[16];                       // final partials

// ---------------- f32x2 packed math (sm_100+) ----------------
#define PACK2(d, lo, hi)   asm("mov.b64 %0, {%1, %2};" : "=l"(d) : "f"(lo), "f"(hi))
#define UNPACK2(lo, hi, s) asm("mov.b64 {%0, %1}, %2;" : "=f"(lo), "=f"(hi) : "l"(s))
#define FMA2(d, a, b, c)   asm("fma.rn.f32x2 %0, %1, %2, %3;" : "=l"(d) : "l"(a), "l"(b), "l"(c))

// ---------------- K0: normalize z (gather from (b,c,h,w)) ----------------
__global__ void znorm_kernel(const float* __restrict__ z) {
    int t = blockIdx.x * 8 + (threadIdx.x >> 5);
    int c = threadIdx.x & 31;
    int b = t >> 8, hw = t & 255;
    float x = z[b * 8192 + c * 256 + hw];
    float s = x * x;
#pragma unroll
    for (int m = 16; m; m >>= 1) s += __shfl_xor_sync(0xffffffffu, s, m);
    float n = sqrtf(s);
    float v = x / fmaxf(n, 1e-12f);
    g_zf[t * DDIM + c] = v;
    float s2 = v * v;
#pragma unroll
    for (int m = 16; m; m >>= 1) s2 += __shfl_xor_sync(0xffffffffu, s2, m);
    if (c == 0) g_zn2[t] = s2;
}

__global__ void enorm_kernel(const float* __restrict__ e) {
    int nrow = blockIdx.x * 8 + (threadIdx.x >> 5);
    int c = threadIdx.x & 31;
    float x = e[nrow * DDIM + c];
    float s = x * x;
#pragma unroll
    for (int m = 16; m; m >>= 1) s += __shfl_xor_sync(0xffffffffu, s, m);
    float n = sqrtf(s);
    float v = x / fmaxf(n, 1e-12f);
    g_en[nrow * DDIM + c] = v;
    float s2 = v * v;
#pragma unroll
    for (int m = 16; m; m >>= 1) s2 += __shfl_xor_sync(0xffffffffu, s2, m);
    if (c == 0) g_en2[nrow] = s2;
}

// ---------------- init (positional filler so p1 is the profiled 4th launch) ----------------
__global__ void init_kernel() {
    int i = blockIdx.x * 256 + threadIdx.x;
    if (i < 16 * N_CODES) g_avgpart[i] = 0.f;
}

// ---------------- P1: 128x128 fp32 GEMM tile + eh store + strip stats ----------------
__global__ void __launch_bounds__(256, 2) p1_kernel() {
    __shared__ float4 esA[DDIM][16];    // codes 8t..8t+3 at dim k (conflict-free)
    __shared__ float4 esB[DDIM][16];    // codes 8t+4..8t+7 at dim k
    __shared__ float  zs[DDIM][128];    // z, k-major (broadcast loads)
    const int tid = threadIdx.x;
    const int c0 = blockIdx.x * 128;
    const int t0 = blockIdx.y * 128;

    const float4* zsrc = (const float4*)(g_zf + (size_t)t0 * DDIM);
    const float4* esrc = (const float4*)(g_en + (size_t)c0 * DDIM);
#pragma unroll
    for (int q = 0; q < 4; q++) {
        int fi = tid + q * 256;
        int row = fi >> 3;          // 0..127
        int col = (fi & 7) << 2;    // k base
        float4 v = zsrc[fi];
        zs[col + 0][row] = v.x;
        zs[col + 1][row] = v.y;
        zs[col + 2][row] = v.z;
        zs[col + 3][row] = v.w;
        float4 w = esrc[fi];
        int t = row >> 3;           // chunk 0..15
        int sub = row & 7;
        float* dst = (sub < 4) ? (float*)esA : (float*)esB;
        int p = sub & 3;
        dst[((col + 0) * 16 + t) * 4 + p] = w.x;
        dst[((col + 1) * 16 + t) * 4 + p] = w.y;
        dst[((col + 2) * 16 + t) * 4 + p] = w.z;
        dst[((col + 3) * 16 + t) * 4 + p] = w.w;
    }
    __syncthreads();

    const int tx = tid & 15, ty = tid >> 4;
    unsigned long long acc[8][4];
#pragma unroll
    for (int i = 0; i < 8; i++)
#pragma unroll
        for (int j = 0; j < 4; j++) acc[i][j] = 0ull;

#pragma unroll 8
    for (int k = 0; k < DDIM; k++) {
        ulonglong2 e01 = *(const ulonglong2*)&esA[k][tx];   // code pairs (0,1),(2,3)
        ulonglong2 e23 = *(const ulonglong2*)&esB[k][tx];   // code pairs (4,5),(6,7)
        float4 za  = *(const float4*)&zs[k][ty * 8];        // broadcast within half-warp
        float4 zb4 = *(const float4*)&zs[k][ty * 8 + 4];
        float zv[8] = {za.x, za.y, za.z, za.w, zb4.x, zb4.y, zb4.z, zb4.w};
#pragma unroll
        for (int i = 0; i < 8; i++) {
            unsigned long long zz;
            PACK2(zz, zv[i], zv[i]);
            FMA2(acc[i][0], e01.x, zz, acc[i][0]);
            FMA2(acc[i][1], e01.y, zz, acc[i][1]);
            FMA2(acc[i][2], e23.x, zz, acc[i][2]);
            FMA2(acc[i][3], e23.y, zz, acc[i][3]);
        }
    }

    // epilogue: fa = fmaf(200, dot, a_t + e2_c); token rows processed in pairs
    float e2v[8];
#pragma unroll
    for (int j = 0; j < 8; j++) e2v[j] = -100.0f * g_en2[c0 + tx * 8 + j];

    const int trow = t0 + ty * 8;
    for (int ii = 0; ii < 8; ii += 2) {
        int tA = trow + ii, tB = trow + ii + 1;
        float aA = -100.0f * g_zn2[tA];
        float aB = -100.0f * g_zn2[tB];
        float favA[8], favB[8];
        float mA = -3.4e38f, mB = -3.4e38f;
        int iA = 0, iB = 0;
#pragma unroll
        for (int jp = 0; jp < 4; jp++) {
            float lo, hi;
            UNPACK2(lo, hi, acc[ii][jp]);
            float f0 = fmaf(200.0f, lo, aA + e2v[2 * jp]);
            float f1 = fmaf(200.0f, hi, aA + e2v[2 * jp + 1]);
            favA[2 * jp] = f0; favA[2 * jp + 1] = f1;
            if (f0 > mA) { mA = f0; iA = c0 + tx * 8 + 2 * jp; }
            if (f1 > mA) { mA = f1; iA = c0 + tx * 8 + 2 * jp + 1; }
            UNPACK2(lo, hi, acc[ii + 1][jp]);
            f0 = fmaf(200.0f, lo, aB + e2v[2 * jp]);
            f1 = fmaf(200.0f, hi, aB + e2v[2 * jp + 1]);
            favB[2 * jp] = f0; favB[2 * jp + 1] = f1;
            if (f0 > mB) { mB = f0; iB = c0 + tx * 8 + 2 * jp; }
            if (f1 > mB) { mB = f1; iB = c0 + tx * 8 + 2 * jp + 1; }
        }
        // interleaved (max, idx) cascades across 16 lanes
#pragma unroll
        for (int s = 1; s < 16; s <<= 1) {
            float omA = __shfl_xor_sync(0xffffffffu, mA, s);
            int   oiA = __shfl_xor_sync(0xffffffffu, iA, s);
            float omB = __shfl_xor_sync(0xffffffffu, mB, s);
            int   oiB = __shfl_xor_sync(0xffffffffu, iB, s);
            if (omA > mA || (omA == mA && oiA < iA)) { mA = omA; iA = oiA; }
            if (omB > mB || (omB == mB && oiB < iB)) { mB = omB; iB = oiB; }
        }
        float SA = 0.f, WA = 0.f, SB = 0.f, WB = 0.f;
        __align__(16) __half2 hA[4];
        __align__(16) __half2 hB[4];
#pragma unroll
        for (int j = 0; j < 8; j += 2) {
            float xA0 = favA[j] - mA, xA1 = favA[j + 1] - mA;
            float eA0 = __expf(xA0), eA1 = __expf(xA1);
            SA += eA0 + eA1;
            WA = fmaf(xA0, eA0, WA); WA = fmaf(xA1, eA1, WA);
            hA[j >> 1] = __floats2half2_rn(eA0, eA1);
            float xB0 = favB[j] - mB, xB1 = favB[j + 1] - mB;
            float eB0 = __expf(xB0), eB1 = __expf(xB1);
            SB += eB0 + eB1;
            WB = fmaf(xB0, eB0, WB); WB = fmaf(xB1, eB1, WB);
            hB[j >> 1] = __floats2half2_rn(eB0, eB1);
        }
        __stcs((uint4*)(g_eh + (size_t)tA * N_CODES + c0 + tx * 8), *(uint4*)hA);
        __stcs((uint4*)(g_eh + (size_t)tB * N_CODES + c0 + tx * 8), *(uint4*)hB);
#pragma unroll
        for (int s = 1; s < 16; s <<= 1) {
            SA += __shfl_xor_sync(0xffffffffu, SA, s);
            WA += __shfl_xor_sync(0xffffffffu, WA, s);
            SB += __shfl_xor_sync(0xffffffffu, SB, s);
            WB += __shfl_xor_sync(0xffffffffu, WB, s);
        }
        if (tx == 0) {
            g_pm[(size_t)tA * NSTRIP + blockIdx.x] = make_float4(mA, SA, WA, __int_as_float(iA));
            g_pm[(size_t)tB * NSTRIP + blockIdx.x] = make_float4(mB, SB, WB, __int_as_float(iB));
        }
    }
}

// ---------------- merge strips per token -> LSE, sample entropy, argmin ----------------
__global__ void merge_kernel() {
    int t = blockIdx.x * 8 + (threadIdx.x >> 5);
    int lane = threadIdx.x & 31;
    float4 v[4];
#pragma unroll
    for (int q = 0; q < 4; q++)
        v[q] = g_pm[(size_t)t * NSTRIP + lane + q * 32];

    float m = v[0].x; int midx = __float_as_int(v[0].w);
#pragma unroll
    for (int q = 1; q < 4; q++) {
        int oi = __float_as_int(v[q].w);
        if (v[q].x > m || (v[q].x == m && oi < midx)) { m = v[q].x; midx = oi; }
    }
#pragma unroll
    for (int s = 1; s < 32; s <<= 1) {
        float om = __shfl_xor_sync(0xffffffffu, m, s);
        int   oi = __shfl_xor_sync(0xffffffffu, midx, s);
        if (om > m || (om == m && oi < midx)) { m = om; midx = oi; }
    }
    float S = 0.f, W = 0.f;
#pragma unroll
    for (int q = 0; q < 4; q++) {
        float dm = v[q].x - m;
        float sc = __expf(dm);
        S += v[q].y * sc;
        W += (v[q].z + dm * v[q].y) * sc;
    }
#pragma unroll
    for (int s = 1; s < 32; s <<= 1) {
        S += __shfl_xor_sync(0xffffffffu, S, s);
        W += __shfl_xor_sync(0xffffffffu, W, s);
    }
    if (lane == 0) {
        float lS = logf(S);
        g_lse[t]  = m + lS;
        g_sent[t] = lS - W / S;
        g_idx[t]  = midx;
    }
}

// ---------------- scale: exp(m_strip - lse) per (token, strip) ----------------
__global__ void scale_kernel() {
    int i = blockIdx.x * 256 + threadIdx.x;   // t*128 + s
    int t = i >> 7;
    g_scale[i] = __expf(g_pm[i].x - g_lse[t]);
}

// ---------------- P2: avg_probs partials from eh * scale ----------------
__global__ void __launch_bounds__(256) p2_kernel() {
    int tid = threadIdx.x;
    int c = blockIdx.x * 512 + tid * 2;
    int t0 = blockIdx.y * 512;
    int s = c >> 7;   // strip fixed per thread (warp-uniform)
    const __half2* eb = (const __half2*)g_eh + ((size_t)t0 * N_CODES + c) / 2;
    const float* scp = g_scale + (size_t)t0 * NSTRIP + s;
    float a0 = 0.f, a1 = 0.f, b0 = 0.f, b1 = 0.f;
#pragma unroll 4
    for (int t = 0; t < 512; t += 2) {
        float sc0 = __ldg(scp + (size_t)t * NSTRIP);
        float sc1 = __ldg(scp + (size_t)(t + 1) * NSTRIP);
        float2 v0 = __half22float2(__ldcs(eb + (size_t)t * (N_CODES / 2)));
        float2 v1 = __half22float2(__ldcs(eb + (size_t)(t + 1) * (N_CODES / 2)));
        a0 = fmaf(v0.x, sc0, a0); a1 = fmaf(v0.y, sc0, a1);
        b0 = fmaf(v1.x, sc1, b0); b1 = fmaf(v1.y, sc1, b1);
    }
    float* op = g_avgpart + (size_t)blockIdx.y * N_CODES + c;
    op[0] = a0 + b0;
    op[1] = a1 + b1;
}

// ---------------- quantize: z_q_st output + vq partials ----------------
__global__ void quant_kernel(float* __restrict__ out) {
    int t = blockIdx.x * 8 + (threadIdx.x >> 5);
    int c = threadIdx.x & 31;
    float zb = g_zf[t * DDIM + c];
    float e = g_en[(size_t)g_idx[t] * DDIM + c];
    float o = zb + (e - zb);
    int b = t >> 8, hw = t & 255;
    out[b * 8192 + c * 256 + hw] = o;
    float df = e - zb;
    float s = df * df;
#pragma unroll
    for (int m = 16; m; m >>= 1) s += __shfl_xor_sync(0xffffffffu, s, m);
    if (c == 0) g_vqtok[t] = s;
}

// ---------------- finalA: parallel partials (10 blocks) ----------------
__global__ void finalA_kernel() {
    __shared__ float red[256];
    int tid = threadIdx.x;
    int b = blockIdx.x;
    float acc = 0.f;
    if (b < 8) {
        int n0 = b * 2048;
        for (int n = n0 + tid; n < n0 + 2048; n += 256) {
            float ap = 0.f;
#pragma unroll
            for (int j = 0; j < 16; j++) ap += g_avgpart[j * N_CODES + n];
            ap *= (1.0f / 8192.0f);
            acc -= ap * logf(ap + 1e-5f);
        }
    } else if (b == 8) {
        for (int t = tid; t < T_TOK; t += 256) acc += g_vqtok[t];
    } else {
        for (int t = tid; t < T_TOK; t += 256) acc += g_sent[t];
    }
    red[tid] = acc; __syncthreads();
    for (int s = 128; s; s >>= 1) { if (tid < s) red[tid] += red[tid + s]; __syncthreads(); }
    if (tid == 0) g_red[b] = red[0];
}

// ---------------- finalB: combine -> 3 loss scalars ----------------
__global__ void finalB_kernel(float* __restrict__ out, int out_size) {
    float ent = 0.f;
#pragma unroll
    for (int j = 0; j < 8; j++) ent += g_red[j];
    float vq = g_red[8] / 262144.0f;
    float se = g_red[9] / 8192.0f;
    out[out_size - 3] = vq;
    out[out_size - 2] = 0.25f * vq;
    out[out_size - 1] = 0.1f * (se - ent);
}

// ---------------- launcher ----------------
extern "C" void kernel_launch(void* const* d_in, const int* in_sizes, int n_in,
                              void* d_out, int out_size) {
    const float* z   = (const float*)d_in[0];
    const float* emb = (const float*)d_in[1];
    float* out = (float*)d_out;

    znorm_kernel<<<T_TOK / 8, 256>>>(z);
    enorm_kernel<<<N_CODES / 8, 256>>>(emb);
    init_kernel<<<(16 * N_CODES) / 256, 256>>>();   // filler: p1 is 4th (profiled) launch

    p1_kernel<<<dim3(NSTRIP, T_TOK / 128), 256>>>();
    merge_kernel<<<T_TOK / 8, 256>>>();
    scale_kernel<<<(T_TOK * NSTRIP) / 256, 256>>>();
    p2_kernel<<<dim3(N_CODES / 512, T_TOK / 512), 256>>>();

    quant_kernel<<<T_TOK / 8, 256>>>(out);
    finalA_kernel<<<10, 256>>>();
    finalB_kernel<<<1, 32>>>(out, out_size);
}

// round 7
// speedup vs baseline: 2.0712x; 1.1426x over previous
#include <cuda_runtime.h>
#include <cuda_fp16.h>
#include <math.h>

#define N_CODES 16384
#define DDIM 32
#define T_TOK 8192
#define NSTRIP 128   // N_CODES / 128 code-strips per token

// ---------------- scratch (static __device__, allowed) ----------------
__device__ float  g_zf[T_TOK * DDIM];              // normalized z, token-major
__device__ float  g_zn2[T_TOK];                    // sum zf^2 per token
__device__ float  g_en[N_CODES * DDIM];            // normalized embedding
__device__ float  g_en2[N_CODES];                  // sum en^2 per code
__device__ __half g_eh[(size_t)T_TOK * N_CODES];   // 256MB: exp(fa - m_strip) fp16
__device__ float4 g_pm[T_TOK * NSTRIP];            // per (token,strip): m, S, W', idx(bits)
__device__ float  g_scale[T_TOK * NSTRIP];         // exp(m_strip - lse_t)
__device__ float  g_lse[T_TOK];
__device__ float  g_sent[T_TOK];                   // per-token sample entropy
__device__ int    g_idx[T_TOK];
__device__ float  g_avgpart[16 * N_CODES];         // avg_probs partials (16 token slabs)
__device__ float  g_vqtok[T_TOK];                  // per-token sum (zq-zb)^2
__device__ float  g_red[16];                       // final partials

// ---------------- f32x2 packed math (sm_100+) ----------------
#define PACK2(d, lo, hi)   asm("mov.b64 %0, {%1, %2};" : "=l"(d) : "f"(lo), "f"(hi))
#define UNPACK2(lo, hi, s) asm("mov.b64 {%0, %1}, %2;" : "=f"(lo), "=f"(hi) : "l"(s))
#define FMA2(d, a, b, c)   asm("fma.rn.f32x2 %0, %1, %2, %3;" : "=l"(d) : "l"(a), "l"(b), "l"(c))

// ---------------- K0: normalize z (gather from (b,c,h,w)) ----------------
__global__ void znorm_kernel(const float* __restrict__ z) {
    int t = blockIdx.x * 8 + (threadIdx.x >> 5);
    int c = threadIdx.x & 31;
    int b = t >> 8, hw = t & 255;
    float x = z[b * 8192 + c * 256 + hw];
    float s = x * x;
#pragma unroll
    for (int m = 16; m; m >>= 1) s += __shfl_xor_sync(0xffffffffu, s, m);
    float n = sqrtf(s);
    float v = x / fmaxf(n, 1e-12f);
    g_zf[t * DDIM + c] = v;
    float s2 = v * v;
#pragma unroll
    for (int m = 16; m; m >>= 1) s2 += __shfl_xor_sync(0xffffffffu, s2, m);
    if (c == 0) g_zn2[t] = s2;
}

__global__ void enorm_kernel(const float* __restrict__ e) {
    int nrow = blockIdx.x * 8 + (threadIdx.x >> 5);
    int c = threadIdx.x & 31;
    float x = e[nrow * DDIM + c];
    float s = x * x;
#pragma unroll
    for (int m = 16; m; m >>= 1) s += __shfl_xor_sync(0xffffffffu, s, m);
    float n = sqrtf(s);
    float v = x / fmaxf(n, 1e-12f);
    g_en[nrow * DDIM + c] = v;
    float s2 = v * v;
#pragma unroll
    for (int m = 16; m; m >>= 1) s2 += __shfl_xor_sync(0xffffffffu, s2, m);
    if (c == 0) g_en2[nrow] = s2;
}

// ---------------- init (positional filler so p1 is the profiled 4th launch) ----------------
__global__ void init_kernel() {
    int i = blockIdx.x * 256 + threadIdx.x;
    if (i < 16 * N_CODES) g_avgpart[i] = 0.f;
}

// ---------------- P1: 128x128 fp32 GEMM tile + eh store + strip stats ----------------
// smem layouts are XOR-swizzled for conflict-free fill AND conflict-free reads:
//   zs:  element (k, row) stored at zs[k][row ^ (((k>>2)&7)<<2)]
//   esA/esB: chunk t (float4 = 4 codes) of dim k stored at chunk index t ^ ((k>>2)&7)
__global__ void __launch_bounds__(256, 2) p1_kernel() {
    __shared__ float4 esA[DDIM][16];
    __shared__ float4 esB[DDIM][16];
    __shared__ float  zs[DDIM][128];
    const int tid = threadIdx.x;
    const int c0 = blockIdx.x * 128;
    const int t0 = blockIdx.y * 128;

    const float4* zsrc = (const float4*)(g_zf + (size_t)t0 * DDIM);
    const float4* esrc = (const float4*)(g_en + (size_t)c0 * DDIM);
#pragma unroll
    for (int q = 0; q < 4; q++) {
        int fi = tid + q * 256;
        int row = fi >> 3;          // 0..127
        int col = (fi & 7) << 2;    // k base: 0,4,...,28
        int cg  = col >> 2;         // (k>>2) for all 4 k's of this thread
        float4 v = zsrc[fi];
        int zr = row ^ (cg << 2);   // swizzled row (bits 2..4)
        zs[col + 0][zr] = v.x;
        zs[col + 1][zr] = v.y;
        zs[col + 2][zr] = v.z;
        zs[col + 3][zr] = v.w;
        float4 w = esrc[fi];
        int t = row >> 3;           // chunk 0..15
        int sub = row & 7;
        float* dst = (sub < 4) ? (float*)esA : (float*)esB;
        int p = sub & 3;
        int tp = t ^ cg;            // swizzled chunk (bits 0..2)
        dst[((col + 0) * 16 + tp) * 4 + p] = w.x;
        dst[((col + 1) * 16 + tp) * 4 + p] = w.y;
        dst[((col + 2) * 16 + tp) * 4 + p] = w.z;
        dst[((col + 3) * 16 + tp) * 4 + p] = w.w;
    }
    __syncthreads();

    const int tx = tid & 15, ty = tid >> 4;
    unsigned long long acc[8][4];
#pragma unroll
    for (int i = 0; i < 8; i++)
#pragma unroll
        for (int j = 0; j < 4; j++) acc[i][j] = 0ull;

#pragma unroll 8
    for (int k = 0; k < DDIM; k++) {
        int swz3 = (k >> 2) & 7;
        ulonglong2 e01 = *(const ulonglong2*)&esA[k][tx ^ swz3];  // codes 8tx+{0,1},{2,3}
        ulonglong2 e23 = *(const ulonglong2*)&esB[k][tx ^ swz3];  // codes 8tx+{4,5},{6,7}
        int rb = (ty * 8) ^ (swz3 << 2);
        float4 za  = *(const float4*)&zs[k][rb];       // rows ty*8+0..3 (in order)
        float4 zb4 = *(const float4*)&zs[k][rb ^ 4];   // rows ty*8+4..7 (in order)
        float zv[8] = {za.x, za.y, za.z, za.w, zb4.x, zb4.y, zb4.z, zb4.w};
#pragma unroll
        for (int i = 0; i < 8; i++) {
            unsigned long long zz;
            PACK2(zz, zv[i], zv[i]);
            FMA2(acc[i][0], e01.x, zz, acc[i][0]);
            FMA2(acc[i][1], e01.y, zz, acc[i][1]);
            FMA2(acc[i][2], e23.x, zz, acc[i][2]);
            FMA2(acc[i][3], e23.y, zz, acc[i][3]);
        }
    }

    // epilogue: fa = fmaf(200, dot, a_t + e2_c); token rows processed in pairs
    float e2v[8];
#pragma unroll
    for (int j = 0; j < 8; j++) e2v[j] = -100.0f * g_en2[c0 + tx * 8 + j];

    const int trow = t0 + ty * 8;
    for (int ii = 0; ii < 8; ii += 2) {
        int tA = trow + ii, tB = trow + ii + 1;
        float aA = -100.0f * g_zn2[tA];
        float aB = -100.0f * g_zn2[tB];
        float favA[8], favB[8];
        float mA = -3.4e38f, mB = -3.4e38f;
        int iA = 0, iB = 0;
#pragma unroll
        for (int jp = 0; jp < 4; jp++) {
            float lo, hi;
            UNPACK2(lo, hi, acc[ii][jp]);
            float f0 = fmaf(200.0f, lo, aA + e2v[2 * jp]);
            float f1 = fmaf(200.0f, hi, aA + e2v[2 * jp + 1]);
            favA[2 * jp] = f0; favA[2 * jp + 1] = f1;
            if (f0 > mA) { mA = f0; iA = c0 + tx * 8 + 2 * jp; }
            if (f1 > mA) { mA = f1; iA = c0 + tx * 8 + 2 * jp + 1; }
            UNPACK2(lo, hi, acc[ii + 1][jp]);
            f0 = fmaf(200.0f, lo, aB + e2v[2 * jp]);
            f1 = fmaf(200.0f, hi, aB + e2v[2 * jp + 1]);
            favB[2 * jp] = f0; favB[2 * jp + 1] = f1;
            if (f0 > mB) { mB = f0; iB = c0 + tx * 8 + 2 * jp; }
            if (f1 > mB) { mB = f1; iB = c0 + tx * 8 + 2 * jp + 1; }
        }
#pragma unroll
        for (int s = 1; s < 16; s <<= 1) {
            float omA = __shfl_xor_sync(0xffffffffu, mA, s);
            int   oiA = __shfl_xor_sync(0xffffffffu, iA, s);
            float omB = __shfl_xor_sync(0xffffffffu, mB, s);
            int   oiB = __shfl_xor_sync(0xffffffffu, iB, s);
            if (omA > mA || (omA == mA && oiA < iA)) { mA = omA; iA = oiA; }
            if (omB > mB || (omB == mB && oiB < iB)) { mB = omB; iB = oiB; }
        }
        float SA = 0.f, WA = 0.f, SB = 0.f, WB = 0.f;
        __align__(16) __half2 hA[4];
        __align__(16) __half2 hB[4];
#pragma unroll
        for (int j = 0; j < 8; j += 2) {
            float xA0 = favA[j] - mA, xA1 = favA[j + 1] - mA;
            float eA0 = __expf(xA0), eA1 = __expf(xA1);
            SA += eA0 + eA1;
            WA = fmaf(xA0, eA0, WA); WA = fmaf(xA1, eA1, WA);
            hA[j >> 1] = __floats2half2_rn(eA0, eA1);
            float xB0 = favB[j] - mB, xB1 = favB[j + 1] - mB;
            float eB0 = __expf(xB0), eB1 = __expf(xB1);
            SB += eB0 + eB1;
            WB = fmaf(xB0, eB0, WB); WB = fmaf(xB1, eB1, WB);
            hB[j >> 1] = __floats2half2_rn(eB0, eB1);
        }
        __stcs((uint4*)(g_eh + (size_t)tA * N_CODES + c0 + tx * 8), *(uint4*)hA);
        __stcs((uint4*)(g_eh + (size_t)tB * N_CODES + c0 + tx * 8), *(uint4*)hB);
#pragma unroll
        for (int s = 1; s < 16; s <<= 1) {
            SA += __shfl_xor_sync(0xffffffffu, SA, s);
            WA += __shfl_xor_sync(0xffffffffu, WA, s);
            SB += __shfl_xor_sync(0xffffffffu, SB, s);
            WB += __shfl_xor_sync(0xffffffffu, WB, s);
        }
        if (tx == 0) {
            g_pm[(size_t)tA * NSTRIP + blockIdx.x] = make_float4(mA, SA, WA, __int_as_float(iA));
            g_pm[(size_t)tB * NSTRIP + blockIdx.x] = make_float4(mB, SB, WB, __int_as_float(iB));
        }
    }
}

// ---------------- merge strips per token -> LSE, sample entropy, argmin ----------------
__global__ void merge_kernel() {
    int t = blockIdx.x * 8 + (threadIdx.x >> 5);
    int lane = threadIdx.x & 31;
    float4 v[4];
#pragma unroll
    for (int q = 0; q < 4; q++)
        v[q] = g_pm[(size_t)t * NSTRIP + lane + q * 32];

    float m = v[0].x; int midx = __float_as_int(v[0].w);
#pragma unroll
    for (int q = 1; q < 4; q++) {
        int oi = __float_as_int(v[q].w);
        if (v[q].x > m || (v[q].x == m && oi < midx)) { m = v[q].x; midx = oi; }
    }
#pragma unroll
    for (int s = 1; s < 32; s <<= 1) {
        float om = __shfl_xor_sync(0xffffffffu, m, s);
        int   oi = __shfl_xor_sync(0xffffffffu, midx, s);
        if (om > m || (om == m && oi < midx)) { m = om; midx = oi; }
    }
    float S = 0.f, W = 0.f;
#pragma unroll
    for (int q = 0; q < 4; q++) {
        float dm = v[q].x - m;
        float sc = __expf(dm);
        S += v[q].y * sc;
        W += (v[q].z + dm * v[q].y) * sc;
    }
#pragma unroll
    for (int s = 1; s < 32; s <<= 1) {
        S += __shfl_xor_sync(0xffffffffu, S, s);
        W += __shfl_xor_sync(0xffffffffu, W, s);
    }
    if (lane == 0) {
        float lS = logf(S);
        g_lse[t]  = m + lS;
        g_sent[t] = lS - W / S;
        g_idx[t]  = midx;
    }
}

// ---------------- scale: exp(m_strip - lse) per (token, strip) ----------------
__global__ void scale_kernel() {
    int i = blockIdx.x * 256 + threadIdx.x;   // t*128 + s
    int t = i >> 7;
    g_scale[i] = __expf(g_pm[i].x - g_lse[t]);
}

// ---------------- P2: avg_probs partials from eh * scale (scales staged in smem) ----------------
__global__ void __launch_bounds__(256) p2_kernel() {
    __shared__ float scs[512 * 4];   // [token 0..511][local strip 0..3]
    int tid = threadIdx.x;
    int bx = blockIdx.x;             // 0..31 (512 codes each)
    int c = bx * 512 + tid * 2;
    int t0 = blockIdx.y * 512;
    for (int i = tid; i < 2048; i += 256) {
        int t = i >> 2, sl = i & 3;
        scs[i] = g_scale[(size_t)(t0 + t) * NSTRIP + bx * 4 + sl];
    }
    __syncthreads();
    int sl = (tid * 2 >> 7) & 3;     // warp-uniform local strip
    const __half2* eb = (const __half2*)g_eh + ((size_t)t0 * N_CODES + c) / 2;
    float a0 = 0.f, a1 = 0.f, b0 = 0.f, b1 = 0.f;
#pragma unroll 4
    for (int t = 0; t < 512; t += 2) {
        float sc0 = scs[t * 4 + sl];
        float sc1 = scs[(t + 1) * 4 + sl];
        float2 v0 = __half22float2(__ldcs(eb + (size_t)t * (N_CODES / 2)));
        float2 v1 = __half22float2(__ldcs(eb + (size_t)(t + 1) * (N_CODES / 2)));
        a0 = fmaf(v0.x, sc0, a0); a1 = fmaf(v0.y, sc0, a1);
        b0 = fmaf(v1.x, sc1, b0); b1 = fmaf(v1.y, sc1, b1);
    }
    float* op = g_avgpart + (size_t)blockIdx.y * N_CODES + c;
    op[0] = a0 + b0;
    op[1] = a1 + b1;
}

// ---------------- quantize: z_q_st output + vq partials ----------------
__global__ void quant_kernel(float* __restrict__ out) {
    int t = blockIdx.x * 8 + (threadIdx.x >> 5);
    int c = threadIdx.x & 31;
    float zb = g_zf[t * DDIM + c];
    float e = g_en[(size_t)g_idx[t] * DDIM + c];
    float o = zb + (e - zb);
    int b = t >> 8, hw = t & 255;
    out[b * 8192 + c * 256 + hw] = o;
    float df = e - zb;
    float s = df * df;
#pragma unroll
    for (int m = 16; m; m >>= 1) s += __shfl_xor_sync(0xffffffffu, s, m);
    if (c == 0) g_vqtok[t] = s;
}

// ---------------- finalA: parallel partials (10 blocks) ----------------
__global__ void finalA_kernel() {
    __shared__ float red[256];
    int tid = threadIdx.x;
    int b = blockIdx.x;
    float acc = 0.f;
    if (b < 8) {
        int n0 = b * 2048;
        for (int n = n0 + tid; n < n0 + 2048; n += 256) {
            float ap = 0.f;
#pragma unroll
            for (int j = 0; j < 16; j++) ap += g_avgpart[j * N_CODES + n];
            ap *= (1.0f / 8192.0f);
            acc -= ap * logf(ap + 1e-5f);
        }
    } else if (b == 8) {
        for (int t = tid; t < T_TOK; t += 256) acc += g_vqtok[t];
    } else {
        for (int t = tid; t < T_TOK; t += 256) acc += g_sent[t];
    }
    red[tid] = acc; __syncthreads();
    for (int s = 128; s; s >>= 1) { if (tid < s) red[tid] += red[tid + s]; __syncthreads(); }
    if (tid == 0) g_red[b] = red[0];
}

// ---------------- finalB: combine -> 3 loss scalars ----------------
__global__ void finalB_kernel(float* __restrict__ out, int out_size) {
    float ent = 0.f;
#pragma unroll
    for (int j = 0; j < 8; j++) ent += g_red[j];
    float vq = g_red[8] / 262144.0f;
    float se = g_red[9] / 8192.0f;
    out[out_size - 3] = vq;
    out[out_size - 2] = 0.25f * vq;
    out[out_size - 1] = 0.1f * (se - ent);
}

// ---------------- launcher ----------------
extern "C" void kernel_launch(void* const* d_in, const int* in_sizes, int n_in,
                              void* d_out, int out_size) {
    const float* z   = (const float*)d_in[0];
    const float* emb = (const float*)d_in[1];
    float* out = (float*)d_out;

    znorm_kernel<<<T_TOK / 8, 256>>>(z);
    enorm_kernel<<<N_CODES / 8, 256>>>(emb);
    init_kernel<<<(16 * N_CODES) / 256, 256>>>();   // filler: p1 is 4th (profiled) launch

    p1_kernel<<<dim3(NSTRIP, T_TOK / 128), 256>>>();
    merge_kernel<<<T_TOK / 8, 256>>>();
    scale_kernel<<<(T_TOK * NSTRIP) / 256, 256>>>();
    p2_kernel<<<dim3(N_CODES / 512, T_TOK / 512), 256>>>();

    quant_kernel<<<T_TOK / 8, 256>>>(out);
    finalA_kernel<<<10, 256>>>();
    finalB_kernel<<<1, 32>>>(out, out_size);
}